// round 4
// baseline (speedup 1.0000x reference)
#include <cuda_runtime.h>

#define NN 8192
#define VV 8
#define OO 16
#define HH 128
#define ROW (4*VV + 3*OO)   // 80 floats per input row
#define TPB 256
#define WPB 8               // warps per block (1 warp = 1 problem row n)
#define NPART (NN / WPB)    // 1024 blocks

// Per-block partials (plain stores; no zeroing kernel)
__device__ float g_pd[NPART];
__device__ float g_po[NPART];
__device__ float g_pv[NPART];
__device__ int   g_oc[NPART];
__device__ int   g_vc[NPART];
__device__ unsigned int g_count;   // zero-init; reset by last block each launch

__inline__ __device__ float warp_red_f(float v) {
    #pragma unroll
    for (int o = 16; o > 0; o >>= 1) v += __shfl_down_sync(0xffffffffu, v, o);
    return v;
}
__inline__ __device__ int warp_red_i(int v) {
    #pragma unroll
    for (int o = 16; o > 0; o >>= 1) v += __shfl_down_sync(0xffffffffu, v, o);
    return v;
}

// Warp layout: lane = v*4 + ch. Vehicle v handles chunk ch of 32 h-steps.
// One warp = one n  =>  obstacle data & prune branch are warp-uniform.
__global__ void __launch_bounds__(TPB) loss_kernel(
    const float* __restrict__ pred,     // (N, V, H) f32
    const float* __restrict__ inputs,   // (N, 80) f32
    float* __restrict__ out)
{
    const int warp = threadIdx.x >> 5;
    const int lane = threadIdx.x & 31;
    const int n  = blockIdx.x * WPB + warp;
    const int v  = lane >> 2;
    const int ch = lane & 3;

    const float* row = inputs + (size_t)n * ROW;

    // ---- obstacles to smem (shared by the warp) ----
    __shared__ float s_ox[WPB][OO], s_oy[WPB][OO], s_r2[WPB][OO];
    float lcx = 0.0f, lcy = 0.0f, lr = 0.0f;
    if (lane < OO) {
        lcx = row[4*VV + 3*lane + 0];
        lcy = row[4*VV + 3*lane + 1];
        lr  = row[4*VV + 3*lane + 2] + 1.0f;    // + OBST_RADIUS
        s_ox[warp][lane] = lcx;
        s_oy[warp][lane] = lcy;
        s_r2[warp][lane] = (lr > 0.0f) ? lr * lr : -1.0f;
    }
    // bbox + rmax via warp reduction (inactive lanes use neutral values)
    float mnx = (lane < OO) ? lcx :  1e30f;
    float mxx = (lane < OO) ? lcx : -1e30f;
    float mny = (lane < OO) ? lcy :  1e30f;
    float mxy = (lane < OO) ? lcy : -1e30f;
    float rmx = (lane < OO) ? lr  : -1e30f;
    #pragma unroll
    for (int o = 16; o > 0; o >>= 1) {
        mnx = fminf(mnx, __shfl_xor_sync(0xffffffffu, mnx, o));
        mxx = fmaxf(mxx, __shfl_xor_sync(0xffffffffu, mxx, o));
        mny = fminf(mny, __shfl_xor_sync(0xffffffffu, mny, o));
        mxy = fmaxf(mxy, __shfl_xor_sync(0xffffffffu, mxy, o));
        rmx = fmaxf(rmx, __shfl_xor_sync(0xffffffffu, rmx, o));
    }
    __syncwarp();
    const float bx0 = mnx - rmx, bx1 = mxx + rmx;
    const float by0 = mny - rmx, by1 = mxy + rmx;

    // ---- vehicle start / target ----
    const float x0 = row[4*v + 0];
    const float y0 = row[4*v + 1];
    const float tx = row[4*v + 2];
    const float ty = row[4*v + 3];

    const float4* p4 =
        (const float4*)(pred + ((size_t)(n * VV + v) * HH + ch * 32));

    // ---- pass 1: chunk sums of cos/sin ----
    float sx = 0.0f, sy = 0.0f;
    #pragma unroll
    for (int i = 0; i < 8; ++i) {
        float4 p = p4[i];
        float s, c;
        __sincosf(p.x, &s, &c); sx += c; sy += s;
        __sincosf(p.y, &s, &c); sx += c; sy += s;
        __sincosf(p.z, &s, &c); sx += c; sy += s;
        __sincosf(p.w, &s, &c); sx += c; sy += s;
    }

    // segmented exclusive prefix over the 4 chunk-lanes of each vehicle
    float ix = sx, iy = sy, t;
    t = __shfl_up_sync(0xffffffffu, ix, 1, 4); if (ch >= 1) ix += t;
    t = __shfl_up_sync(0xffffffffu, iy, 1, 4); if (ch >= 1) iy += t;
    t = __shfl_up_sync(0xffffffffu, ix, 2, 4); if (ch >= 2) ix += t;
    t = __shfl_up_sync(0xffffffffu, iy, 2, 4); if (ch >= 2) iy += t;
    float x = fmaf(2.0f, ix - sx, x0);   // STEP = 2
    float y = fmaf(2.0f, iy - sy, y0);

    // ---- pass 2: walk 32 steps with correct offsets ----
    float dist_sum = 0.0f, oinv = 0.0f, vinv = 0.0f;
    int ocnt = 0, vcnt = 0;
    const bool vact = (v < 7);

    #pragma unroll 1
    for (int i = 0; i < 8; ++i) {
        float4 p = p4[i];
        float pv[4] = {p.x, p.y, p.z, p.w};
        #pragma unroll
        for (int j = 0; j < 4; ++j) {
            float s, c;
            __sincosf(pv[j], &s, &c);
            x = fmaf(2.0f, c, x);
            y = fmaf(2.0f, s, y);

            // target-distance term
            float dx = tx - x, dy = ty - y;
            float td2 = fmaxf(fmaf(dx, dx, dy * dy), 1e-30f);
            dist_sum += td2 * rsqrtf(td2);

            // obstacle term (exact bbox prune; warp-uniform data)
            if (x >= bx0 && x <= bx1 && y >= by0 && y <= by1) {
                #pragma unroll
                for (int o = 0; o < OO; ++o) {
                    float ax = x - s_ox[warp][o];
                    float ay = y - s_oy[warp][o];
                    float d2 = fmaf(ax, ax, ay * ay);
                    if (d2 < s_r2[warp][o]) { oinv += rsqrtf(d2); ocnt++; }
                }
            }

            // vehicle-vehicle term: vehicle v+1 same chunk = lane+4
            float xn = __shfl_down_sync(0xffffffffu, x, 4);
            float yn = __shfl_down_sync(0xffffffffu, y, 4);
            if (vact) {
                float bxv = xn - x, byv = yn - y;
                float d2 = fmaf(bxv, bxv, byv * byv);
                if (d2 < 1.0f) { vinv += rsqrtf(d2); vcnt++; }  // VEH_RADIUS^2=1
            }
        }
    }

    // ---- warp -> block reduction ----
    dist_sum = warp_red_f(dist_sum);
    oinv     = warp_red_f(oinv);
    vinv     = warp_red_f(vinv);
    ocnt     = warp_red_i(ocnt);
    vcnt     = warp_red_i(vcnt);

    __shared__ float sd[WPB], so[WPB], sv[WPB];
    __shared__ int soc[WPB], svc[WPB];
    if (lane == 0) {
        sd[warp] = dist_sum; so[warp] = oinv; sv[warp] = vinv;
        soc[warp] = ocnt; svc[warp] = vcnt;
    }
    __syncthreads();
    if (warp == 0) {
        float d = (lane < WPB) ? sd[lane] : 0.0f;
        float a = (lane < WPB) ? so[lane] : 0.0f;
        float b = (lane < WPB) ? sv[lane] : 0.0f;
        int   c = (lane < WPB) ? soc[lane] : 0;
        int   e = (lane < WPB) ? svc[lane] : 0;
        d = warp_red_f(d); a = warp_red_f(a); b = warp_red_f(b);
        c = warp_red_i(c); e = warp_red_i(e);
        if (lane == 0) {
            g_pd[blockIdx.x] = d;
            g_po[blockIdx.x] = a;
            g_pv[blockIdx.x] = b;
            g_oc[blockIdx.x] = c;
            g_vc[blockIdx.x] = e;
        }
    }

    // ---- last-block finalize (no separate kernel) ----
    __shared__ bool isLast;
    __threadfence();
    if (threadIdx.x == 0) {
        unsigned int prev = atomicAdd(&g_count, 1u);
        isLast = (prev == NPART - 1);
    }
    __syncthreads();
    if (!isLast) return;

    float d = 0.0f, a = 0.0f, b = 0.0f;
    int c = 0, e = 0;
    #pragma unroll
    for (int i = 0; i < NPART / TPB; ++i) {
        int idx = threadIdx.x + i * TPB;
        d += g_pd[idx]; a += g_po[idx]; b += g_pv[idx];
        c += g_oc[idx]; e += g_vc[idx];
    }
    d = warp_red_f(d); a = warp_red_f(a); b = warp_red_f(b);
    c = warp_red_i(c); e = warp_red_i(e);
    if (lane == 0) {
        sd[warp] = d; so[warp] = a; sv[warp] = b; soc[warp] = c; svc[warp] = e;
    }
    __syncthreads();
    if (warp == 0) {
        d = (lane < WPB) ? sd[lane] : 0.0f;
        a = (lane < WPB) ? so[lane] : 0.0f;
        b = (lane < WPB) ? sv[lane] : 0.0f;
        c = (lane < WPB) ? soc[lane] : 0;
        e = (lane < WPB) ? svc[lane] : 0;
        d = warp_red_f(d); a = warp_red_f(a); b = warp_red_f(b);
        c = warp_red_i(c); e = warp_red_i(e);
        if (lane == 0) {
            double loss = (double)d / ((double)NN * VV * HH);     // DIST_COST=1
            if (c > 0) loss += ((double)a / (double)c) * 0.1;     // OBST_COST
            if (e > 0) loss += ((double)b / (double)e) * 0.1;     // VEH_COST
            out[0] = (float)loss;
            g_count = 0;   // reset for next graph replay
        }
    }
}

extern "C" void kernel_launch(void* const* d_in, const int* in_sizes, int n_in,
                              void* d_out, int out_size) {
    const float* pred   = (const float*)d_in[0];   // (N, V, H, 1) f32
    const float* inputs = (const float*)d_in[1];   // (N, 80) f32
    float* out = (float*)d_out;

    loss_kernel<<<NPART, TPB>>>(pred, inputs, out);
}

// round 5
// speedup vs baseline: 1.2492x; 1.2492x over previous
#include <cuda_runtime.h>

#define NN 8192
#define VV 8
#define OO 16
#define HH 128
#define ROW (4*VV + 3*OO)   // 80 floats per input row
#define TPB 256
#define WPB 8               // warps per block (1 warp = 1 problem row n)
#define NPART (NN / WPB)    // 1024 blocks

// Per-block partials (plain stores; no zeroing kernel)
__device__ float g_pd[NPART];   // phase A: dist sums
__device__ float g_pv[NPART];   // phase A: vehicle 1/d sums
__device__ int   g_vc[NPART];   // phase A: vehicle counts
__device__ float g_po[NPART];   // phase B: obstacle 1/d sums
__device__ int   g_oc[NPART];   // phase B: obstacle counts
__device__ unsigned int g_done; // zero-init; last block resets each launch

// Worklist of in-box trajectory points, bucketed by n.
// Capacity V*H = 1024 per n is the exact worst case -> no overflow possible.
__device__ float2 g_wl[NN][VV * HH];
__device__ int    g_wcnt[NN];

__inline__ __device__ float warp_red_f(float v) {
    #pragma unroll
    for (int o = 16; o > 0; o >>= 1) v += __shfl_down_sync(0xffffffffu, v, o);
    return v;
}
__inline__ __device__ int warp_red_i(int v) {
    #pragma unroll
    for (int o = 16; o > 0; o >>= 1) v += __shfl_down_sync(0xffffffffu, v, o);
    return v;
}

// ============================ Phase A =====================================
// Warp layout: lane = v*4 + ch. Vehicle v, chunk ch of 32 h-steps.
// One warp = one n => worklist index is warp-private (no atomics).
__global__ void __launch_bounds__(TPB) traj_kernel(
    const float* __restrict__ pred,     // (N, V, H) f32
    const float* __restrict__ inputs)   // (N, 80) f32
{
    const int warp = threadIdx.x >> 5;
    const int lane = threadIdx.x & 31;
    const int n  = blockIdx.x * WPB + warp;
    const int v  = lane >> 2;
    const int ch = lane & 3;

    const float* row = inputs + (size_t)n * ROW;

    // exact prune box from obstacle centers + max effective radius
    float lcx = 0.0f, lcy = 0.0f, lr = 0.0f;
    if (lane < OO) {
        lcx = row[4*VV + 3*lane + 0];
        lcy = row[4*VV + 3*lane + 1];
        lr  = row[4*VV + 3*lane + 2] + 1.0f;    // + OBST_RADIUS
    }
    float mnx = (lane < OO) ? lcx :  1e30f;
    float mxx = (lane < OO) ? lcx : -1e30f;
    float mny = (lane < OO) ? lcy :  1e30f;
    float mxy = (lane < OO) ? lcy : -1e30f;
    float rmx = (lane < OO) ? lr  : -1e30f;
    #pragma unroll
    for (int o = 16; o > 0; o >>= 1) {
        mnx = fminf(mnx, __shfl_xor_sync(0xffffffffu, mnx, o));
        mxx = fmaxf(mxx, __shfl_xor_sync(0xffffffffu, mxx, o));
        mny = fminf(mny, __shfl_xor_sync(0xffffffffu, mny, o));
        mxy = fmaxf(mxy, __shfl_xor_sync(0xffffffffu, mxy, o));
        rmx = fmaxf(rmx, __shfl_xor_sync(0xffffffffu, rmx, o));
    }
    const float bx0 = mnx - rmx, bx1 = mxx + rmx;
    const float by0 = mny - rmx, by1 = mxy + rmx;

    const float x0 = row[4*v + 0];
    const float y0 = row[4*v + 1];
    const float tx = row[4*v + 2];
    const float ty = row[4*v + 3];

    const float4* p4 =
        (const float4*)(pred + ((size_t)(n * VV + v) * HH + ch * 32));

    // pass 1: chunk sums of cos/sin
    float sx = 0.0f, sy = 0.0f;
    #pragma unroll
    for (int i = 0; i < 8; ++i) {
        float4 p = p4[i];
        float s, c;
        __sincosf(p.x, &s, &c); sx += c; sy += s;
        __sincosf(p.y, &s, &c); sx += c; sy += s;
        __sincosf(p.z, &s, &c); sx += c; sy += s;
        __sincosf(p.w, &s, &c); sx += c; sy += s;
    }
    // segmented exclusive prefix over the 4 chunk-lanes of each vehicle
    float ix = sx, iy = sy, t;
    t = __shfl_up_sync(0xffffffffu, ix, 1, 4); if (ch >= 1) ix += t;
    t = __shfl_up_sync(0xffffffffu, iy, 1, 4); if (ch >= 1) iy += t;
    t = __shfl_up_sync(0xffffffffu, ix, 2, 4); if (ch >= 2) ix += t;
    t = __shfl_up_sync(0xffffffffu, iy, 2, 4); if (ch >= 2) iy += t;
    float x = fmaf(2.0f, ix - sx, x0);   // STEP = 2
    float y = fmaf(2.0f, iy - sy, y0);

    // pass 2: walk 32 steps; emit in-box points to the worklist
    float dist_sum = 0.0f, vinv = 0.0f;
    int vcnt = 0;
    int wl_base = 0;                       // warp-uniform running count
    const unsigned lt_mask = (1u << lane) - 1u;
    const bool vact = (v < 7);
    float2* wl = g_wl[n];

    #pragma unroll 1
    for (int i = 0; i < 8; ++i) {
        float4 p = p4[i];
        float pv[4] = {p.x, p.y, p.z, p.w};
        #pragma unroll
        for (int j = 0; j < 4; ++j) {
            float s, c;
            __sincosf(pv[j], &s, &c);
            x = fmaf(2.0f, c, x);
            y = fmaf(2.0f, s, y);

            // target-distance term
            float dx = tx - x, dy = ty - y;
            float td2 = fmaxf(fmaf(dx, dx, dy * dy), 1e-30f);
            dist_sum += td2 * rsqrtf(td2);

            // in-box test -> compact append (warp-aggregated, no atomics)
            bool inbox = (x >= bx0) & (x <= bx1) & (y >= by0) & (y <= by1);
            unsigned m = __ballot_sync(0xffffffffu, inbox);
            if (inbox)
                wl[wl_base + __popc(m & lt_mask)] = make_float2(x, y);
            wl_base += __popc(m);

            // vehicle-vehicle term: vehicle v+1 same chunk = lane+4
            float xn = __shfl_down_sync(0xffffffffu, x, 4);
            float yn = __shfl_down_sync(0xffffffffu, y, 4);
            if (vact) {
                float bxv = xn - x, byv = yn - y;
                float d2 = fmaf(bxv, bxv, byv * byv);
                if (d2 < 1.0f) { vinv += rsqrtf(d2); vcnt++; }  // VEH_R^2=1
            }
        }
    }
    if (lane == 0) g_wcnt[n] = wl_base;    // plain store, no zeroing needed

    // warp -> block reduction of dist/vehicle terms
    dist_sum = warp_red_f(dist_sum);
    vinv     = warp_red_f(vinv);
    vcnt     = warp_red_i(vcnt);

    __shared__ float sd[WPB], sv[WPB];
    __shared__ int   svc[WPB];
    if (lane == 0) { sd[warp] = dist_sum; sv[warp] = vinv; svc[warp] = vcnt; }
    __syncthreads();
    if (warp == 0) {
        float d = (lane < WPB) ? sd[lane] : 0.0f;
        float b = (lane < WPB) ? sv[lane] : 0.0f;
        int   e = (lane < WPB) ? svc[lane] : 0;
        d = warp_red_f(d); b = warp_red_f(b); e = warp_red_i(e);
        if (lane == 0) {
            g_pd[blockIdx.x] = d;
            g_pv[blockIdx.x] = b;
            g_vc[blockIdx.x] = e;
        }
    }
}

// ============================ Phase B =====================================
// Warp per n: dense obstacle pass over the compacted worklist.
__global__ void __launch_bounds__(TPB) obst_kernel(float* __restrict__ out,
                                                   const float* __restrict__ inputs)
{
    const int warp = threadIdx.x >> 5;
    const int lane = threadIdx.x & 31;
    const int n = blockIdx.x * WPB + warp;

    const float* row = inputs + (size_t)n * ROW;

    __shared__ float s_ox[WPB][OO], s_oy[WPB][OO], s_r2[WPB][OO];
    if (lane < OO) {
        float r = row[4*VV + 3*lane + 2] + 1.0f;
        s_ox[warp][lane] = row[4*VV + 3*lane + 0];
        s_oy[warp][lane] = row[4*VV + 3*lane + 1];
        s_r2[warp][lane] = (r > 0.0f) ? r * r : -1.0f;
    }
    __syncwarp();

    const int cnt = g_wcnt[n];
    const float2* wl = g_wl[n];

    float oinv = 0.0f;
    int ocnt = 0;
    for (int i = lane; i < cnt; i += 32) {
        float2 pt = wl[i];
        #pragma unroll
        for (int o = 0; o < OO; ++o) {
            float ax = pt.x - s_ox[warp][o];
            float ay = pt.y - s_oy[warp][o];
            float d2 = fmaf(ax, ax, ay * ay);
            if (d2 < s_r2[warp][o]) { oinv += rsqrtf(d2); ocnt++; }
        }
    }

    oinv = warp_red_f(oinv);
    ocnt = warp_red_i(ocnt);

    __shared__ float so[WPB];
    __shared__ int soc[WPB];
    if (lane == 0) { so[warp] = oinv; soc[warp] = ocnt; }
    __syncthreads();
    if (warp == 0) {
        float a = (lane < WPB) ? so[lane] : 0.0f;
        int   c = (lane < WPB) ? soc[lane] : 0;
        a = warp_red_f(a); c = warp_red_i(c);
        if (lane == 0) { g_po[blockIdx.x] = a; g_oc[blockIdx.x] = c; }
    }

    // ---- last-block finalize ----
    __shared__ bool isLast;
    __threadfence();
    if (threadIdx.x == 0) {
        unsigned int prev = atomicAdd(&g_done, 1u);
        isLast = (prev == NPART - 1);
    }
    __syncthreads();
    if (!isLast) return;

    float d = 0.0f, a = 0.0f, b = 0.0f;
    int c = 0, e = 0;
    #pragma unroll
    for (int i = 0; i < NPART / TPB; ++i) {
        int idx = threadIdx.x + i * TPB;
        d += g_pd[idx]; a += g_po[idx]; b += g_pv[idx];
        c += g_oc[idx]; e += g_vc[idx];
    }
    d = warp_red_f(d); a = warp_red_f(a); b = warp_red_f(b);
    c = warp_red_i(c); e = warp_red_i(e);

    __shared__ float fd[WPB], fa[WPB], fb[WPB];
    __shared__ int fc[WPB], fe[WPB];
    if (lane == 0) { fd[warp] = d; fa[warp] = a; fb[warp] = b; fc[warp] = c; fe[warp] = e; }
    __syncthreads();
    if (warp == 0) {
        d = (lane < WPB) ? fd[lane] : 0.0f;
        a = (lane < WPB) ? fa[lane] : 0.0f;
        b = (lane < WPB) ? fb[lane] : 0.0f;
        c = (lane < WPB) ? fc[lane] : 0;
        e = (lane < WPB) ? fe[lane] : 0;
        d = warp_red_f(d); a = warp_red_f(a); b = warp_red_f(b);
        c = warp_red_i(c); e = warp_red_i(e);
        if (lane == 0) {
            double loss = (double)d / ((double)NN * VV * HH);   // DIST_COST=1
            if (c > 0) loss += ((double)a / (double)c) * 0.1;   // OBST_COST
            if (e > 0) loss += ((double)b / (double)e) * 0.1;   // VEH_COST
            out[0] = (float)loss;
            g_done = 0;   // reset for next graph replay
        }
    }
}

extern "C" void kernel_launch(void* const* d_in, const int* in_sizes, int n_in,
                              void* d_out, int out_size) {
    const float* pred   = (const float*)d_in[0];   // (N, V, H, 1) f32
    const float* inputs = (const float*)d_in[1];   // (N, 80) f32
    float* out = (float*)d_out;

    traj_kernel<<<NPART, TPB>>>(pred, inputs);
    obst_kernel<<<NPART, TPB>>>(out, inputs);
}

// round 6
// speedup vs baseline: 1.3966x; 1.1180x over previous
#include <cuda_runtime.h>

#define NN 8192
#define VV 8
#define OO 16
#define HH 128
#define ROW (4*VV + 3*OO)   // 80 floats per input row
#define TPB 256
#define WPB 8               // warps per block (1 warp = 1 problem row n)
#define NPART (NN / WPB)    // 1024 blocks
#define BUFCAP 64           // smem drain buffer entries per warp (max pending 31+32)

// Per-block partials (plain stores; no zeroing kernel)
__device__ float g_pd[NPART];
__device__ float g_po[NPART];
__device__ float g_pv[NPART];
__device__ int   g_oc[NPART];
__device__ int   g_vc[NPART];
__device__ unsigned int g_done;   // zero-init; last block resets each launch

__inline__ __device__ float warp_red_f(float v) {
    #pragma unroll
    for (int o = 16; o > 0; o >>= 1) v += __shfl_down_sync(0xffffffffu, v, o);
    return v;
}
__inline__ __device__ int warp_red_i(int v) {
    #pragma unroll
    for (int o = 16; o > 0; o >>= 1) v += __shfl_down_sync(0xffffffffu, v, o);
    return v;
}

// Warp layout: lane = v*4 + ch. Vehicle v, chunk ch of 32 h-steps.
// One warp = one n  =>  obstacle data, prune box, and drain-buffer state are
// warp-uniform; compaction indices come from ballot/popc (no atomics).
__global__ void __launch_bounds__(TPB) loss_kernel(
    const float* __restrict__ pred,     // (N, V, H) f32
    const float* __restrict__ inputs,   // (N, 80) f32
    float* __restrict__ out)
{
    const int warp = threadIdx.x >> 5;
    const int lane = threadIdx.x & 31;
    const int n  = blockIdx.x * WPB + warp;
    const int v  = lane >> 2;
    const int ch = lane & 3;

    const float* row = inputs + (size_t)n * ROW;

    // ---- obstacles -> smem; prune box via warp reductions ----
    __shared__ float  s_ox[WPB][OO], s_oy[WPB][OO], s_r2[WPB][OO];
    __shared__ float2 s_buf[WPB][BUFCAP];

    float lcx = 0.0f, lcy = 0.0f, lr = 0.0f;
    if (lane < OO) {
        lcx = row[4*VV + 3*lane + 0];
        lcy = row[4*VV + 3*lane + 1];
        lr  = row[4*VV + 3*lane + 2] + 1.0f;     // + OBST_RADIUS
        s_ox[warp][lane] = lcx;
        s_oy[warp][lane] = lcy;
        s_r2[warp][lane] = (lr > 0.0f) ? lr * lr : -1.0f;
    }
    float mnx = (lane < OO) ? lcx :  1e30f;
    float mxx = (lane < OO) ? lcx : -1e30f;
    float mny = (lane < OO) ? lcy :  1e30f;
    float mxy = (lane < OO) ? lcy : -1e30f;
    float rmx = (lane < OO) ? lr  : -1e30f;
    #pragma unroll
    for (int o = 16; o > 0; o >>= 1) {
        mnx = fminf(mnx, __shfl_xor_sync(0xffffffffu, mnx, o));
        mxx = fmaxf(mxx, __shfl_xor_sync(0xffffffffu, mxx, o));
        mny = fminf(mny, __shfl_xor_sync(0xffffffffu, mny, o));
        mxy = fmaxf(mxy, __shfl_xor_sync(0xffffffffu, mxy, o));
        rmx = fmaxf(rmx, __shfl_xor_sync(0xffffffffu, rmx, o));
    }
    __syncwarp();
    // box as center/half-extent: inbox = |x-cbx|<=hbx && |y-cby|<=hby
    const float cbx = 0.5f * (mnx + mxx), hbx = 0.5f * (mxx - mnx) + rmx;
    const float cby = 0.5f * (mny + mxy), hby = 0.5f * (mxy - mny) + rmx;

    const float x0 = row[4*v + 0];
    const float y0 = row[4*v + 1];
    const float tx = row[4*v + 2];
    const float ty = row[4*v + 3];

    const float4* p4 =
        (const float4*)(pred + ((size_t)(n * VV + v) * HH + ch * 32));

    // ---- pass 1: chunk sums of cos/sin ----
    float sx = 0.0f, sy = 0.0f;
    #pragma unroll
    for (int i = 0; i < 8; ++i) {
        float4 p = p4[i];
        float s, c;
        __sincosf(p.x, &s, &c); sx += c; sy += s;
        __sincosf(p.y, &s, &c); sx += c; sy += s;
        __sincosf(p.z, &s, &c); sx += c; sy += s;
        __sincosf(p.w, &s, &c); sx += c; sy += s;
    }
    // segmented exclusive prefix over the 4 chunk-lanes of each vehicle
    float ix = sx, iy = sy, t;
    t = __shfl_up_sync(0xffffffffu, ix, 1, 4); if (ch >= 1) ix += t;
    t = __shfl_up_sync(0xffffffffu, iy, 1, 4); if (ch >= 1) iy += t;
    t = __shfl_up_sync(0xffffffffu, ix, 2, 4); if (ch >= 2) ix += t;
    t = __shfl_up_sync(0xffffffffu, iy, 2, 4); if (ch >= 2) iy += t;
    float x = fmaf(2.0f, ix - sx, x0);   // STEP = 2
    float y = fmaf(2.0f, iy - sy, y0);

    // ---- pass 2: walk 32 steps; compact in-box points; drain inline ----
    float dist_sum = 0.0f, oinv = 0.0f, vinv = 0.0f;
    int ocnt = 0, vcnt = 0;
    int pending = 0;                       // warp-uniform buffered count
    const unsigned lt_mask = (1u << lane) - 1u;
    const bool vact = (v < 7);

    #pragma unroll 1
    for (int i = 0; i < 8; ++i) {
        float4 p = p4[i];
        float pv[4] = {p.x, p.y, p.z, p.w};
        #pragma unroll
        for (int j = 0; j < 4; ++j) {
            float s, c;
            __sincosf(pv[j], &s, &c);
            x = fmaf(2.0f, c, x);
            y = fmaf(2.0f, s, y);

            // target-distance term
            float dx = tx - x, dy = ty - y;
            float td2 = fmaxf(fmaf(dx, dx, dy * dy), 1e-30f);
            dist_sum += td2 * rsqrtf(td2);

            // in-box -> compact append to smem buffer
            bool inbox = (fabsf(x - cbx) <= hbx) & (fabsf(y - cby) <= hby);
            unsigned m = __ballot_sync(0xffffffffu, inbox);
            if (inbox)
                s_buf[warp][pending + __popc(m & lt_mask)] = make_float2(x, y);
            pending += __popc(m);

            // vehicle-vehicle term: vehicle v+1 same chunk = lane+4
            float xn = __shfl_down_sync(0xffffffffu, x, 4);
            float yn = __shfl_down_sync(0xffffffffu, y, 4);
            if (vact) {
                float bxv = xn - x, byv = yn - y;
                float d2 = fmaf(bxv, bxv, byv * byv);
                if (d2 < 1.0f) { vinv += rsqrtf(d2); vcnt++; }  // VEH_R^2 = 1
            }

            // drain 32 points densely (warp-uniform branch)
            if (pending >= 32) {
                __syncwarp();
                float2 q = s_buf[warp][lane];
                #pragma unroll
                for (int o = 0; o < OO; ++o) {
                    float ax = q.x - s_ox[warp][o];
                    float ay = q.y - s_oy[warp][o];
                    float d2 = fmaf(ax, ax, ay * ay);
                    if (d2 < s_r2[warp][o]) { oinv += rsqrtf(d2); ocnt++; }
                }
                int rem = pending - 32;
                float2 mv;
                if (lane < rem) mv = s_buf[warp][32 + lane];
                __syncwarp();
                if (lane < rem) s_buf[warp][lane] = mv;
                pending = rem;
            }
        }
    }

    // final flush of the partial buffer
    if (pending > 0) {
        __syncwarp();
        if (lane < pending) {
            float2 q = s_buf[warp][lane];
            #pragma unroll
            for (int o = 0; o < OO; ++o) {
                float ax = q.x - s_ox[warp][o];
                float ay = q.y - s_oy[warp][o];
                float d2 = fmaf(ax, ax, ay * ay);
                if (d2 < s_r2[warp][o]) { oinv += rsqrtf(d2); ocnt++; }
            }
        }
    }

    // ---- warp -> block reduction ----
    dist_sum = warp_red_f(dist_sum);
    oinv     = warp_red_f(oinv);
    vinv     = warp_red_f(vinv);
    ocnt     = warp_red_i(ocnt);
    vcnt     = warp_red_i(vcnt);

    __shared__ float sd[WPB], so[WPB], sv[WPB];
    __shared__ int soc[WPB], svc[WPB];
    if (lane == 0) {
        sd[warp] = dist_sum; so[warp] = oinv; sv[warp] = vinv;
        soc[warp] = ocnt; svc[warp] = vcnt;
    }
    __syncthreads();
    if (warp == 0) {
        float d = (lane < WPB) ? sd[lane] : 0.0f;
        float a = (lane < WPB) ? so[lane] : 0.0f;
        float b = (lane < WPB) ? sv[lane] : 0.0f;
        int   c = (lane < WPB) ? soc[lane] : 0;
        int   e = (lane < WPB) ? svc[lane] : 0;
        d = warp_red_f(d); a = warp_red_f(a); b = warp_red_f(b);
        c = warp_red_i(c); e = warp_red_i(e);
        if (lane == 0) {
            g_pd[blockIdx.x] = d;
            g_po[blockIdx.x] = a;
            g_pv[blockIdx.x] = b;
            g_oc[blockIdx.x] = c;
            g_vc[blockIdx.x] = e;
        }
    }

    // ---- last-block finalize ----
    __shared__ bool isLast;
    __threadfence();
    if (threadIdx.x == 0) {
        unsigned int prev = atomicAdd(&g_done, 1u);
        isLast = (prev == NPART - 1);
    }
    __syncthreads();
    if (!isLast) return;

    float d = 0.0f, a = 0.0f, b = 0.0f;
    int c = 0, e = 0;
    #pragma unroll
    for (int i = 0; i < NPART / TPB; ++i) {
        int idx = threadIdx.x + i * TPB;
        d += g_pd[idx]; a += g_po[idx]; b += g_pv[idx];
        c += g_oc[idx]; e += g_vc[idx];
    }
    d = warp_red_f(d); a = warp_red_f(a); b = warp_red_f(b);
    c = warp_red_i(c); e = warp_red_i(e);
    if (lane == 0) {
        sd[warp] = d; so[warp] = a; sv[warp] = b; soc[warp] = c; svc[warp] = e;
    }
    __syncthreads();
    if (warp == 0) {
        d = (lane < WPB) ? sd[lane] : 0.0f;
        a = (lane < WPB) ? so[lane] : 0.0f;
        b = (lane < WPB) ? sv[lane] : 0.0f;
        c = (lane < WPB) ? soc[lane] : 0;
        e = (lane < WPB) ? svc[lane] : 0;
        d = warp_red_f(d); a = warp_red_f(a); b = warp_red_f(b);
        c = warp_red_i(c); e = warp_red_i(e);
        if (lane == 0) {
            double loss = (double)d / ((double)NN * VV * HH);   // DIST_COST=1
            if (c > 0) loss += ((double)a / (double)c) * 0.1;   // OBST_COST
            if (e > 0) loss += ((double)b / (double)e) * 0.1;   // VEH_COST
            out[0] = (float)loss;
            g_done = 0;   // reset for next graph replay
        }
    }
}

extern "C" void kernel_launch(void* const* d_in, const int* in_sizes, int n_in,
                              void* d_out, int out_size) {
    const float* pred   = (const float*)d_in[0];   // (N, V, H, 1) f32
    const float* inputs = (const float*)d_in[1];   // (N, 80) f32
    float* out = (float*)d_out;

    loss_kernel<<<NPART, TPB>>>(pred, inputs, out);
}